// round 2
// baseline (speedup 1.0000x reference)
#include <cuda_runtime.h>
#include <math.h>

// Problem constants (from reference setup_inputs)
#define HEADS 8
#define HID 64
#define HCdim 512
#define NMAXc 50000
#define EMAXc 450000   // 400000 edges + 50000 self loops

// ---------------- scratch (static __device__ — no allocation allowed) ----------------
__device__ __align__(16) float    g_x  [NMAXc * HCdim];   // layer input features
__device__ __align__(16) float    g_hw [NMAXc * HCdim];   // h = x @ W  [N, H, C]
__device__ __align__(16) float    g_out[NMAXc * HCdim];   // aggregation output
__device__ __align__(16) float    g_as [NMAXc * HEADS];
__device__ __align__(16) float    g_ad [NMAXc * HEADS];
__device__ __align__(16) unsigned g_mx [NMAXc * HEADS];   // ordered-uint encoded max
__device__ __align__(16) float    g_sm [NMAXc * HEADS];   // softmax denom
__device__ __align__(16) float    g_e  [EMAXc * HEADS];   // edge scores, then exp()
__device__ int g_src[EMAXc];
__device__ int g_dst[EMAXc];
__device__ int g_is64;

// ---------------- helpers ----------------
__device__ __forceinline__ unsigned f2o(float f) {
    unsigned u = __float_as_uint(f);
    return (u & 0x80000000u) ? ~u : (u | 0x80000000u);
}
__device__ __forceinline__ float o2f(unsigned u) {
    return __uint_as_float((u & 0x80000000u) ? (u ^ 0x80000000u) : ~u);
}
__device__ __forceinline__ void red_add_v4(float* a, float4 v) {
    asm volatile("red.global.add.v4.f32 [%0], {%1,%2,%3,%4};"
                 :: "l"(a), "f"(v.x), "f"(v.y), "f"(v.z), "f"(v.w) : "memory");
}

// ---------------- edge index dtype probe + decode ----------------
// If the harness kept int64, every value in the first 64 entries (viewed as
// int64) lies in [0,N). If it downcast to int32, the int64 view fuses pairs
// of indices into huge numbers -> probe fails decisively.
__global__ void detect_kernel(const void* __restrict__ ei, int E0, int N) {
    if (threadIdx.x == 0 && blockIdx.x == 0) {
        const long long* p = (const long long*)ei;
        int K = E0 < 64 ? E0 : 64;
        int ok = 1;
        for (int i = 0; i < K; i++) {
            long long v = p[i];
            if (v < 0 || v >= N) { ok = 0; break; }
        }
        g_is64 = ok;
    }
}

__global__ void decode_kernel(const void* __restrict__ ei, int E0, int N) {
    int e = blockIdx.x * blockDim.x + threadIdx.x;
    int Et = E0 + N;
    if (e >= Et) return;
    int s, d;
    if (e < E0) {
        if (g_is64) {
            const long long* p = (const long long*)ei;
            s = (int)p[e]; d = (int)p[E0 + e];
        } else {
            const int* p = (const int*)ei;
            s = p[e]; d = p[E0 + e];
        }
    } else {
        s = d = e - E0;
    }
    // clamp defensively (no-op for valid data)
    s = min(max(s, 0), N - 1);
    d = min(max(d, 0), N - 1);
    g_src[e] = s;
    g_dst[e] = d;
}

// ---------------- layer-1 GEMM: [N,18] @ [18,512] ----------------
__global__ void gemm18_kernel(const float* __restrict__ x, const float* __restrict__ W, int N) {
    __shared__ float sW[18 * 512];
    __shared__ float sx[8 * 18];
    for (int i = threadIdx.x; i < 18 * 512; i += 256) sW[i] = W[i];
    int n0 = blockIdx.x * 8;
    for (int i = threadIdx.x; i < 8 * 18; i += 256) {
        int n = n0 + i / 18;
        sx[i] = (n < N) ? x[n * 18 + i % 18] : 0.f;
    }
    __syncthreads();
    for (int o = threadIdx.x; o < 8 * 512; o += 256) {
        int nl = o >> 9, c = o & 511;
        int n = n0 + nl;
        if (n < N) {
            float acc = 0.f;
#pragma unroll
            for (int k = 0; k < 18; k++) acc += sx[nl * 18 + k] * sW[k * 512 + c];
            g_hw[n * 512 + c] = acc;
        }
    }
}

// ---------------- layers 2/3 GEMM: g_x [M,512] @ W [512,512] -> g_hw ----------------
__global__ __launch_bounds__(256, 2) void sgemm512_kernel(const float* __restrict__ B, int M) {
    const int K = 512, Nn = 512;
    __shared__ float As[16][128];
    __shared__ float Bs[16][64];
    int tid = threadIdx.x;
    int tx = tid & 15, ty = tid >> 4;
    int rowBase = blockIdx.y * 128, colBase = blockIdx.x * 64;
    int aRow = tid >> 1, aK = (tid & 1) << 3;
    int bRow = tid >> 4, bCol = (tid & 15) << 2;
    float acc[8][4];
#pragma unroll
    for (int i = 0; i < 8; i++)
#pragma unroll
        for (int j = 0; j < 4; j++) acc[i][j] = 0.f;

    for (int k0 = 0; k0 < K; k0 += 16) {
        int gr = rowBase + aRow;
        float4 a0 = make_float4(0.f, 0.f, 0.f, 0.f), a1 = a0;
        if (gr < M) {
            const float4* p = (const float4*)&g_x[gr * K + k0 + aK];
            a0 = p[0];
            a1 = p[1];
        }
        As[aK + 0][aRow] = a0.x; As[aK + 1][aRow] = a0.y;
        As[aK + 2][aRow] = a0.z; As[aK + 3][aRow] = a0.w;
        As[aK + 4][aRow] = a1.x; As[aK + 5][aRow] = a1.y;
        As[aK + 6][aRow] = a1.z; As[aK + 7][aRow] = a1.w;
        *(float4*)&Bs[bRow][bCol] = *(const float4*)&B[(k0 + bRow) * Nn + colBase + bCol];
        __syncthreads();
#pragma unroll
        for (int k = 0; k < 16; k++) {
            float4 b4 = *(const float4*)&Bs[k][tx << 2];
            float4 x0 = *(const float4*)&As[k][ty << 3];
            float4 x1 = *(const float4*)&As[k][(ty << 3) + 4];
            float am[8] = {x0.x, x0.y, x0.z, x0.w, x1.x, x1.y, x1.z, x1.w};
            float bn[4] = {b4.x, b4.y, b4.z, b4.w};
#pragma unroll
            for (int i = 0; i < 8; i++)
#pragma unroll
                for (int j = 0; j < 4; j++) acc[i][j] += am[i] * bn[j];
        }
        __syncthreads();
    }
#pragma unroll
    for (int i = 0; i < 8; i++) {
        int r = rowBase + (ty << 3) + i;
        if (r < M)
            *(float4*)&g_hw[r * Nn + colBase + (tx << 2)] =
                make_float4(acc[i][0], acc[i][1], acc[i][2], acc[i][3]);
    }
}

// ---------------- per-node attention coefficients ----------------
__global__ void alpha_kernel(const float* __restrict__ a_src, const float* __restrict__ a_dst, int N) {
    int gw = (blockIdx.x * blockDim.x + threadIdx.x) >> 5;
    int lane = threadIdx.x & 31;
    if (gw >= N * 8) return;
    int n = gw >> 3, h = gw & 7;
    const float* hp = &g_hw[n * 512 + h * 64];
    float v0 = hp[lane], v1 = hp[lane + 32];
    const float* sp = &a_src[h * 64];
    const float* dp = &a_dst[h * 64];
    float ds = v0 * sp[lane] + v1 * sp[lane + 32];
    float dd = v0 * dp[lane] + v1 * dp[lane + 32];
#pragma unroll
    for (int o = 16; o; o >>= 1) {
        ds += __shfl_xor_sync(0xffffffffu, ds, o);
        dd += __shfl_xor_sync(0xffffffffu, dd, o);
    }
    if (!lane) { g_as[gw] = ds; g_ad[gw] = dd; }
}

// ---------------- per-layer init: out=bias, sum=0, max=-inf ----------------
__global__ void init_kernel(const float* __restrict__ bias, int N) {
    int i = blockIdx.x * blockDim.x + threadIdx.x;
    if (i < N * 512) g_out[i] = bias ? bias[i & 511] : 0.f;
    if (i < N * 8) { g_sm[i] = 0.f; g_mx[i] = 0x007FFFFFu; /* f2o(-inf) */ }
}

// ---------------- edge pass 1: e = leakyrelu(as[src]+ad[dst]); segment max ----------------
__global__ void pass1_kernel(int Et) {
    int e = blockIdx.x * blockDim.x + threadIdx.x;
    if (e >= Et) return;
    int s = g_src[e], d = g_dst[e];
    float4 s0 = *(const float4*)&g_as[s * 8];
    float4 s1 = *(const float4*)&g_as[s * 8 + 4];
    float4 d0 = *(const float4*)&g_ad[d * 8];
    float4 d1 = *(const float4*)&g_ad[d * 8 + 4];
    float eh[8] = {s0.x + d0.x, s0.y + d0.y, s0.z + d0.z, s0.w + d0.w,
                   s1.x + d1.x, s1.y + d1.y, s1.z + d1.z, s1.w + d1.w};
#pragma unroll
    for (int h = 0; h < 8; h++) {
        float v = eh[h];
        v = v > 0.f ? v : 0.2f * v;
        eh[h] = v;
        atomicMax(&g_mx[d * 8 + h], f2o(v));
    }
    *(float4*)&g_e[e * 8]     = make_float4(eh[0], eh[1], eh[2], eh[3]);
    *(float4*)&g_e[e * 8 + 4] = make_float4(eh[4], eh[5], eh[6], eh[7]);
}

// ---------------- edge pass 2: ex = exp(e - max[dst]); segment sum ----------------
__global__ void pass2_kernel(int Et) {
    int e = blockIdx.x * blockDim.x + threadIdx.x;
    if (e >= Et) return;
    int d = g_dst[e];
    float4 e0 = *(const float4*)&g_e[e * 8];
    float4 e1 = *(const float4*)&g_e[e * 8 + 4];
    float eh[8] = {e0.x, e0.y, e0.z, e0.w, e1.x, e1.y, e1.z, e1.w};
    float ex[8];
#pragma unroll
    for (int h = 0; h < 8; h++) ex[h] = __expf(eh[h] - o2f(g_mx[d * 8 + h]));
    *(float4*)&g_e[e * 8]     = make_float4(ex[0], ex[1], ex[2], ex[3]);
    *(float4*)&g_e[e * 8 + 4] = make_float4(ex[4], ex[5], ex[6], ex[7]);
    red_add_v4(&g_sm[d * 8],     make_float4(ex[0], ex[1], ex[2], ex[3]));
    red_add_v4(&g_sm[d * 8 + 4], make_float4(ex[4], ex[5], ex[6], ex[7]));
}

// ---------------- edge pass 3: out[dst] += h[src] * alpha  (one block per edge) ----------------
__global__ void agg_kernel(int Et) {
    __shared__ float sw[8];
    int e = blockIdx.x;
    int tid = threadIdx.x;
    int s = g_src[e], d = g_dst[e];
    if (tid < 8) sw[tid] = g_e[e * 8 + tid] * __fdividef(1.f, g_sm[d * 8 + tid] + 1e-16f);
    __syncthreads();
    int head = tid >> 4, c = (tid & 15) << 2;
    float w = sw[head];
    float4 v = *(const float4*)&g_hw[s * 512 + head * 64 + c];
    red_add_v4(&g_out[d * 512 + head * 64 + c],
               make_float4(v.x * w, v.y * w, v.z * w, v.w * w));
}

// ---------------- activations / epilogues ----------------
__global__ void elu_kernel(int N) {
    int i = blockIdx.x * blockDim.x + threadIdx.x;
    if (i < N * 512) {
        float v = g_out[i];
        g_x[i] = v > 0.f ? v : expm1f(v);
    }
}

__global__ void mean_kernel(const float* __restrict__ b3, int N) {
    int i = blockIdx.x * blockDim.x + threadIdx.x;
    if (i >= N * 64) return;
    int n = i >> 6, c = i & 63;
    float acc = 0.f;
#pragma unroll
    for (int h = 0; h < 8; h++) acc += g_out[n * 512 + h * 64 + c];
    g_x[n * 64 + c] = acc * 0.125f + b3[c];
}

__global__ void final_kernel(const float* __restrict__ Wo, const float* __restrict__ bo,
                             float* __restrict__ out, int N) {
    __shared__ float sW[64 * 15];
    __shared__ float sb[15];
    for (int i = threadIdx.x; i < 64 * 15; i += 256) sW[i] = Wo[i];
    if (threadIdx.x < 15) sb[threadIdx.x] = bo[threadIdx.x];
    __syncthreads();
    int gid = blockIdx.x * 256 + threadIdx.x;
    if (gid >= N * 15) return;
    int n = gid / 15, o = gid - n * 15;
    float acc = sb[o];
#pragma unroll
    for (int c = 0; c < 64; c++) acc += g_x[n * 64 + c] * sW[c * 15 + o];
    out[gid] = acc;
}

// ---------------- launch ----------------
extern "C" void kernel_launch(void* const* d_in, const int* in_sizes, int n_in,
                              void* d_out, int out_size) {
    const float* x   = (const float*)d_in[0];
    const void*  ei  = (const void*)d_in[1];
    const float* W1  = (const float*)d_in[2];
    const float* a1s = (const float*)d_in[3];
    const float* a1d = (const float*)d_in[4];
    const float* b1  = (const float*)d_in[5];
    const float* W2  = (const float*)d_in[6];
    const float* a2s = (const float*)d_in[7];
    const float* a2d = (const float*)d_in[8];
    const float* b2  = (const float*)d_in[9];
    const float* W3  = (const float*)d_in[10];
    const float* a3s = (const float*)d_in[11];
    const float* a3d = (const float*)d_in[12];
    const float* b3  = (const float*)d_in[13];
    const float* Wo  = (const float*)d_in[14];
    const float* bo  = (const float*)d_in[15];

    int N  = in_sizes[0] / 18;
    int E0 = in_sizes[1] / 2;
    int Et = E0 + N;

    int gNH = (N * 512 + 255) / 256;
    int gE  = (Et + 255) / 256;
    int gA  = (N * 8 * 32 + 255) / 256;
    dim3 gG(8, (N + 127) / 128);

    detect_kernel<<<1, 32>>>(ei, E0, N);
    decode_kernel<<<gE, 256>>>(ei, E0, N);

    // ---- layer 1 (concat, ELU) ----
    gemm18_kernel<<<(N + 7) / 8, 256>>>(x, W1, N);
    alpha_kernel<<<gA, 256>>>(a1s, a1d, N);
    init_kernel<<<gNH, 256>>>(b1, N);
    pass1_kernel<<<gE, 256>>>(Et);
    pass2_kernel<<<gE, 256>>>(Et);
    agg_kernel<<<Et, 128>>>(Et);
    elu_kernel<<<gNH, 256>>>(N);

    // ---- layer 2 (concat, ELU) ----
    sgemm512_kernel<<<gG, 256>>>(W2, N);
    alpha_kernel<<<gA, 256>>>(a2s, a2d, N);
    init_kernel<<<gNH, 256>>>(b2, N);
    pass1_kernel<<<gE, 256>>>(Et);
    pass2_kernel<<<gE, 256>>>(Et);
    agg_kernel<<<Et, 128>>>(Et);
    elu_kernel<<<gNH, 256>>>(N);

    // ---- layer 3 (mean over heads) ----
    sgemm512_kernel<<<gG, 256>>>(W3, N);
    alpha_kernel<<<gA, 256>>>(a3s, a3d, N);
    init_kernel<<<gNH, 256>>>(nullptr, N);
    pass1_kernel<<<gE, 256>>>(Et);
    pass2_kernel<<<gE, 256>>>(Et);
    agg_kernel<<<Et, 128>>>(Et);
    mean_kernel<<<(N * 64 + 255) / 256, 256>>>(b3, N);

    // ---- final projection ----
    final_kernel<<<(N * 15 + 255) / 256, 256>>>(Wo, bo, (float*)d_out, N);
}

// round 3
// speedup vs baseline: 1.6192x; 1.6192x over previous
#include <cuda_runtime.h>
#include <math.h>

#define HEADS 8
#define HID 64
#define HCdim 512
#define NMAXc 50000
#define EMAXc 450000   // 400000 edges + 50000 self loops

// ---------------- scratch ----------------
__device__ __align__(16) float g_x  [NMAXc * HCdim];   // layer input / elu output
__device__ __align__(16) float g_hw [NMAXc * HCdim];   // h = x @ W
__device__ __align__(16) float g_out[NMAXc * HCdim];   // layer-3 raw aggregation
__device__ __align__(16) float g_as [NMAXc * HEADS];
__device__ __align__(16) float g_ad [NMAXc * HEADS];
__device__ int g_src[EMAXc];
__device__ int g_dst[EMAXc];
__device__ int g_eidx[EMAXc];        // src ids grouped by dst (CSR)
__device__ int g_cnt[NMAXc];
__device__ int g_off[NMAXc + 1];
__device__ int g_pos[NMAXc];
__device__ int g_is64;

// ---------------- edge index dtype probe + decode ----------------
__global__ void detect_kernel(const void* __restrict__ ei, int E0, int N) {
    if (threadIdx.x == 0 && blockIdx.x == 0) {
        const long long* p = (const long long*)ei;
        int K = E0 < 64 ? E0 : 64;
        int ok = 1;
        for (int i = 0; i < K; i++) {
            long long v = p[i];
            if (v < 0 || v >= N) { ok = 0; break; }
        }
        g_is64 = ok;
    }
}

__global__ void decode_kernel(const void* __restrict__ ei, int E0, int N) {
    int e = blockIdx.x * blockDim.x + threadIdx.x;
    int Et = E0 + N;
    if (e >= Et) return;
    int s, d;
    if (e < E0) {
        if (g_is64) {
            const long long* p = (const long long*)ei;
            s = (int)p[e]; d = (int)p[E0 + e];
        } else {
            const int* p = (const int*)ei;
            s = p[e]; d = p[E0 + e];
        }
    } else {
        s = d = e - E0;
    }
    s = min(max(s, 0), N - 1);
    d = min(max(d, 0), N - 1);
    g_src[e] = s;
    g_dst[e] = d;
}

// ---------------- CSR build ----------------
__global__ void zero_cnt_kernel(int N) {
    int i = blockIdx.x * blockDim.x + threadIdx.x;
    if (i < N) g_cnt[i] = 0;
}
__global__ void hist_kernel(int Et) {
    int e = blockIdx.x * blockDim.x + threadIdx.x;
    if (e < Et) atomicAdd(&g_cnt[g_dst[e]], 1);
}
__global__ void scan_kernel(int N) {
    __shared__ int s[256];
    int tid = threadIdx.x;
    int carry = 0;
    for (int base = 0; base < N; base += 256) {
        int v = (base + tid < N) ? g_cnt[base + tid] : 0;
        s[tid] = v;
        __syncthreads();
#pragma unroll
        for (int off = 1; off < 256; off <<= 1) {
            int t = (tid >= off) ? s[tid - off] : 0;
            __syncthreads();
            s[tid] += t;
            __syncthreads();
        }
        int total = s[255];
        if (base + tid < N) {
            int e = carry + s[tid] - v;
            g_off[base + tid] = e;
            g_pos[base + tid] = e;
        }
        carry += total;
        __syncthreads();
    }
    if (tid == 0) g_off[N] = carry;
}
__global__ void scatter_kernel(int Et) {
    int e = blockIdx.x * blockDim.x + threadIdx.x;
    if (e >= Et) return;
    int d = g_dst[e];
    int idx = atomicAdd(&g_pos[d], 1);
    g_eidx[idx] = g_src[e];
}

// ---------------- layer-1 GEMM: [N,18] @ [18,512] ----------------
__global__ void gemm18_kernel(const float* __restrict__ x, const float* __restrict__ W, int N) {
    __shared__ float sW[18 * 512];
    __shared__ float sx[32 * 18];
    for (int i = threadIdx.x; i < 18 * 512; i += 256) sW[i] = W[i];
    int n0 = blockIdx.x * 32;
    for (int i = threadIdx.x; i < 32 * 18; i += 256) {
        int n = n0 + i / 18;
        sx[i] = (n < N) ? x[n * 18 + i % 18] : 0.f;
    }
    __syncthreads();
    for (int o = threadIdx.x; o < 32 * 512; o += 256) {
        int nl = o >> 9, c = o & 511;
        int n = n0 + nl;
        if (n < N) {
            float acc = 0.f;
#pragma unroll
            for (int k = 0; k < 18; k++) acc += sx[nl * 18 + k] * sW[k * 512 + c];
            g_hw[n * 512 + c] = acc;
        }
    }
}

// ---------------- layers 2/3 GEMM: g_x [M,512] @ B [512,512] -> g_hw ----------------
// 128x128 tile, 8x8 per thread, split row/col layout for bank-clean LDS.128
__global__ __launch_bounds__(256, 2) void sgemm128_kernel(const float* __restrict__ B, int M) {
    const int K = 512, Nn = 512;
    __shared__ float As[16][128];
    __shared__ float Bs[16][128];
    int tid = threadIdx.x;
    int tx = tid & 15, ty = tid >> 4;
    int rowBase = blockIdx.y * 128, colBase = blockIdx.x * 128;
    int aRow = tid >> 1, aK = (tid & 1) << 3;
    int bRow = tid >> 4, bCol = (tid & 15) << 3;
    float acc[8][8];
#pragma unroll
    for (int i = 0; i < 8; i++)
#pragma unroll
        for (int j = 0; j < 8; j++) acc[i][j] = 0.f;

    for (int k0 = 0; k0 < K; k0 += 16) {
        int gr = rowBase + aRow;
        float4 a0 = make_float4(0.f, 0.f, 0.f, 0.f), a1 = a0;
        if (gr < M) {
            const float4* p = (const float4*)&g_x[(size_t)gr * K + k0 + aK];
            a0 = p[0]; a1 = p[1];
        }
        As[aK + 0][aRow] = a0.x; As[aK + 1][aRow] = a0.y;
        As[aK + 2][aRow] = a0.z; As[aK + 3][aRow] = a0.w;
        As[aK + 4][aRow] = a1.x; As[aK + 5][aRow] = a1.y;
        As[aK + 6][aRow] = a1.z; As[aK + 7][aRow] = a1.w;
        {
            const float4* p = (const float4*)&B[(size_t)(k0 + bRow) * Nn + colBase + bCol];
            *(float4*)&Bs[bRow][bCol] = p[0];
            *(float4*)&Bs[bRow][bCol + 4] = p[1];
        }
        __syncthreads();
#pragma unroll
        for (int k = 0; k < 16; k++) {
            float4 a0v = *(const float4*)&As[k][ty << 2];
            float4 a1v = *(const float4*)&As[k][64 + (ty << 2)];
            float4 b0v = *(const float4*)&Bs[k][tx << 2];
            float4 b1v = *(const float4*)&Bs[k][64 + (tx << 2)];
            float am[8] = {a0v.x, a0v.y, a0v.z, a0v.w, a1v.x, a1v.y, a1v.z, a1v.w};
            float bn[8] = {b0v.x, b0v.y, b0v.z, b0v.w, b1v.x, b1v.y, b1v.z, b1v.w};
#pragma unroll
            for (int i = 0; i < 8; i++)
#pragma unroll
                for (int j = 0; j < 8; j++) acc[i][j] += am[i] * bn[j];
        }
        __syncthreads();
    }
#pragma unroll
    for (int i = 0; i < 8; i++) {
        int r = rowBase + ((i < 4) ? ((ty << 2) + i) : (64 + (ty << 2) + i - 4));
        if (r < M) {
            *(float4*)&g_hw[(size_t)r * Nn + colBase + (tx << 2)] =
                make_float4(acc[i][0], acc[i][1], acc[i][2], acc[i][3]);
            *(float4*)&g_hw[(size_t)r * Nn + colBase + 64 + (tx << 2)] =
                make_float4(acc[i][4], acc[i][5], acc[i][6], acc[i][7]);
        }
    }
}

// ---------------- per-node attention coefficients ----------------
__global__ void alpha_kernel(const float* __restrict__ a_src, const float* __restrict__ a_dst, int N) {
    int gw = (blockIdx.x * blockDim.x + threadIdx.x) >> 5;
    int lane = threadIdx.x & 31;
    if (gw >= N * 8) return;
    int n = gw >> 3, h = gw & 7;
    const float* hp = &g_hw[(size_t)n * 512 + h * 64];
    float v0 = hp[lane], v1 = hp[lane + 32];
    const float* sp = &a_src[h * 64];
    const float* dp = &a_dst[h * 64];
    float ds = v0 * sp[lane] + v1 * sp[lane + 32];
    float dd = v0 * dp[lane] + v1 * dp[lane + 32];
#pragma unroll
    for (int o = 16; o; o >>= 1) {
        ds += __shfl_xor_sync(0xffffffffu, ds, o);
        dd += __shfl_xor_sync(0xffffffffu, dd, o);
    }
    if (!lane) { g_as[gw] = ds; g_ad[gw] = dd; }
}

// ---------------- fused per-dst softmax + aggregation (CSR, no atomics) ----------------
// MODE 0: out = elu(acc + bias) -> g_x     (layers 1,2)
// MODE 1: out = acc             -> g_out   (layer 3; mean kernel adds bias)
template <int MODE>
__global__ __launch_bounds__(128) void agg_csr_kernel(const float* __restrict__ bias) {
    int d = blockIdx.x;
    int tid = threadIdx.x;
    int beg = g_off[d], end = g_off[d + 1];

    __shared__ float s_m[8], s_den[8];
    __shared__ float s_part[64];
    __shared__ float s_w[16 * 8];
    __shared__ int   s_src[16];

    // phase 1a: per-head max over incoming edges (64 threads: 8 heads x 8 slots)
    if (tid < 64) {
        int h = tid & 7, slot = tid >> 3;
        float adh = g_ad[d * 8 + h];
        float m = -1e30f;
        for (int j = beg + slot; j < end; j += 8) {
            float v = g_as[g_eidx[j] * 8 + h] + adh;
            v = v > 0.f ? v : 0.2f * v;
            m = fmaxf(m, v);
        }
        s_part[tid] = m;
    }
    __syncthreads();
    if (tid < 8) {
        float m = s_part[tid];
#pragma unroll
        for (int k = 1; k < 8; k++) m = fmaxf(m, s_part[tid + 8 * k]);
        s_m[tid] = m;
    }
    __syncthreads();
    // phase 1b: per-head exp-sum
    if (tid < 64) {
        int h = tid & 7, slot = tid >> 3;
        float adh = g_ad[d * 8 + h], m = s_m[h], den = 0.f;
        for (int j = beg + slot; j < end; j += 8) {
            float v = g_as[g_eidx[j] * 8 + h] + adh;
            v = v > 0.f ? v : 0.2f * v;
            den += __expf(v - m);
        }
        s_part[tid] = den;
    }
    __syncthreads();
    if (tid < 8) {
        float den = 0.f;
#pragma unroll
        for (int k = 0; k < 8; k++) den += s_part[tid + 8 * k];
        s_den[tid] = __fdividef(1.f, den + 1e-16f);
    }

    // phase 2: weighted aggregation, chunks of 16 edges
    int head = tid >> 4;
    float4 acc = make_float4(0.f, 0.f, 0.f, 0.f);
    for (int c0 = beg; c0 < end; c0 += 16) {
        int nc = min(16, end - c0);
        __syncthreads();
        if (tid < nc) s_src[tid] = g_eidx[c0 + tid];
        __syncthreads();
        {
            int j = tid >> 3, h = tid & 7;
            if (j < nc) {
                float v = g_as[s_src[j] * 8 + h] + g_ad[d * 8 + h];
                v = v > 0.f ? v : 0.2f * v;
                s_w[j * 8 + h] = __expf(v - s_m[h]) * s_den[h];
            }
        }
        __syncthreads();
#pragma unroll 4
        for (int j = 0; j < nc; j++) {
            float w = s_w[j * 8 + head];
            float4 hv = *(const float4*)&g_hw[(size_t)s_src[j] * 512 + tid * 4];
            acc.x += hv.x * w; acc.y += hv.y * w;
            acc.z += hv.z * w; acc.w += hv.w * w;
        }
    }

    if (MODE == 0) {
        float4 bb = *(const float4*)&bias[tid * 4];
        acc.x += bb.x; acc.y += bb.y; acc.z += bb.z; acc.w += bb.w;
        acc.x = acc.x > 0.f ? acc.x : expm1f(acc.x);
        acc.y = acc.y > 0.f ? acc.y : expm1f(acc.y);
        acc.z = acc.z > 0.f ? acc.z : expm1f(acc.z);
        acc.w = acc.w > 0.f ? acc.w : expm1f(acc.w);
        *(float4*)&g_x[(size_t)d * 512 + tid * 4] = acc;
    } else {
        *(float4*)&g_out[(size_t)d * 512 + tid * 4] = acc;
    }
}

// ---------------- epilogues ----------------
__global__ void mean_kernel(const float* __restrict__ b3, int N) {
    int i = blockIdx.x * blockDim.x + threadIdx.x;
    if (i >= N * 64) return;
    int n = i >> 6, c = i & 63;
    float acc = 0.f;
#pragma unroll
    for (int h = 0; h < 8; h++) acc += g_out[(size_t)n * 512 + h * 64 + c];
    g_x[n * 64 + c] = acc * 0.125f + b3[c];
}

__global__ void final_kernel(const float* __restrict__ Wo, const float* __restrict__ bo,
                             float* __restrict__ out, int N) {
    __shared__ float sW[64 * 15];
    __shared__ float sb[15];
    for (int i = threadIdx.x; i < 64 * 15; i += 256) sW[i] = Wo[i];
    if (threadIdx.x < 15) sb[threadIdx.x] = bo[threadIdx.x];
    __syncthreads();
    int gid = blockIdx.x * 256 + threadIdx.x;
    if (gid >= N * 15) return;
    int n = gid / 15, o = gid - n * 15;
    float acc = sb[o];
#pragma unroll
    for (int c = 0; c < 64; c++) acc += g_x[n * 64 + c] * sW[c * 15 + o];
    out[gid] = acc;
}

// ---------------- launch ----------------
extern "C" void kernel_launch(void* const* d_in, const int* in_sizes, int n_in,
                              void* d_out, int out_size) {
    const float* x   = (const float*)d_in[0];
    const void*  ei  = (const void*)d_in[1];
    const float* W1  = (const float*)d_in[2];
    const float* a1s = (const float*)d_in[3];
    const float* a1d = (const float*)d_in[4];
    const float* b1  = (const float*)d_in[5];
    const float* W2  = (const float*)d_in[6];
    const float* a2s = (const float*)d_in[7];
    const float* a2d = (const float*)d_in[8];
    const float* b2  = (const float*)d_in[9];
    const float* W3  = (const float*)d_in[10];
    const float* a3s = (const float*)d_in[11];
    const float* a3d = (const float*)d_in[12];
    const float* b3  = (const float*)d_in[13];
    const float* Wo  = (const float*)d_in[14];
    const float* bo  = (const float*)d_in[15];

    int N  = in_sizes[0] / 18;
    int E0 = in_sizes[1] / 2;
    int Et = E0 + N;

    int gE = (Et + 255) / 256;
    int gN = (N + 255) / 256;
    int gA = (N * 8 * 32 + 255) / 256;
    dim3 gG(4, (N + 127) / 128);

    // edge decode + CSR build (once)
    detect_kernel<<<1, 32>>>(ei, E0, N);
    decode_kernel<<<gE, 256>>>(ei, E0, N);
    zero_cnt_kernel<<<gN, 256>>>(N);
    hist_kernel<<<gE, 256>>>(Et);
    scan_kernel<<<1, 256>>>(N);
    scatter_kernel<<<gE, 256>>>(Et);

    // ---- layer 1 ----
    gemm18_kernel<<<(N + 31) / 32, 256>>>(x, W1, N);
    alpha_kernel<<<gA, 256>>>(a1s, a1d, N);
    agg_csr_kernel<0><<<N, 128>>>(b1);

    // ---- layer 2 ----
    sgemm128_kernel<<<gG, 256>>>(W2, N);
    alpha_kernel<<<gA, 256>>>(a2s, a2d, N);
    agg_csr_kernel<0><<<N, 128>>>(b2);

    // ---- layer 3 ----
    sgemm128_kernel<<<gG, 256>>>(W3, N);
    alpha_kernel<<<gA, 256>>>(a3s, a3d, N);
    agg_csr_kernel<1><<<N, 128>>>(nullptr);

    mean_kernel<<<(N * 64 + 255) / 256, 256>>>(b3, N);
    final_kernel<<<(N * 15 + 255) / 256, 256>>>(Wo, bo, (float*)d_out, N);
}

// round 4
// speedup vs baseline: 2.8520x; 1.7614x over previous
#include <cuda_runtime.h>
#include <math.h>

#define HEADS 8
#define HID 64
#define HCdim 512
#define NMAXc 50000
#define EMAXc 450000   // 400000 edges + 50000 self loops

// ---------------- scratch ----------------
__device__ __align__(16) float g_x  [NMAXc * HCdim];   // layer input / elu output
__device__ __align__(16) float g_hw [NMAXc * HCdim];   // h = x @ W
__device__ __align__(16) float g_out[NMAXc * HCdim];   // layer-3 raw aggregation
__device__ __align__(16) float g_as [NMAXc * HEADS];
__device__ __align__(16) float g_ad [NMAXc * HEADS];
__device__ int g_src[EMAXc];
__device__ int g_dst[EMAXc];
__device__ int g_eidx[EMAXc];        // src ids grouped by dst (CSR)
__device__ int g_cnt[NMAXc];
__device__ int g_off[NMAXc + 1];
__device__ int g_pos[NMAXc];
__device__ int g_is64;

// ---------------- helpers ----------------
__device__ __forceinline__ unsigned f2tf(float f) {
    unsigned r;
    asm("cvt.rna.tf32.f32 %0, %1;" : "=r"(r) : "f"(f));
    return r;
}
__device__ __forceinline__ void mma_tf32(float* c, const unsigned* a, const unsigned* b) {
    asm volatile(
        "mma.sync.aligned.m16n8k8.row.col.f32.tf32.tf32.f32 "
        "{%0,%1,%2,%3}, {%4,%5,%6,%7}, {%8,%9}, {%0,%1,%2,%3};"
        : "+f"(c[0]), "+f"(c[1]), "+f"(c[2]), "+f"(c[3])
        : "r"(a[0]), "r"(a[1]), "r"(a[2]), "r"(a[3]), "r"(b[0]), "r"(b[1]));
}

// ---------------- edge index dtype probe + decode ----------------
__global__ void detect_kernel(const void* __restrict__ ei, int E0, int N) {
    if (threadIdx.x == 0 && blockIdx.x == 0) {
        const long long* p = (const long long*)ei;
        int K = E0 < 64 ? E0 : 64;
        int ok = 1;
        for (int i = 0; i < K; i++) {
            long long v = p[i];
            if (v < 0 || v >= N) { ok = 0; break; }
        }
        g_is64 = ok;
    }
}

__global__ void decode_kernel(const void* __restrict__ ei, int E0, int N) {
    int e = blockIdx.x * blockDim.x + threadIdx.x;
    int Et = E0 + N;
    if (e >= Et) return;
    int s, d;
    if (e < E0) {
        if (g_is64) {
            const long long* p = (const long long*)ei;
            s = (int)p[e]; d = (int)p[E0 + e];
        } else {
            const int* p = (const int*)ei;
            s = p[e]; d = p[E0 + e];
        }
    } else {
        s = d = e - E0;
    }
    s = min(max(s, 0), N - 1);
    d = min(max(d, 0), N - 1);
    g_src[e] = s;
    g_dst[e] = d;
}

// ---------------- CSR build ----------------
__global__ void zero_cnt_kernel(int N) {
    int i = blockIdx.x * blockDim.x + threadIdx.x;
    if (i < N) g_cnt[i] = 0;
}
__global__ void hist_kernel(int Et) {
    int e = blockIdx.x * blockDim.x + threadIdx.x;
    if (e < Et) atomicAdd(&g_cnt[g_dst[e]], 1);
}
__global__ void scan_kernel(int N) {
    __shared__ int s_w[8];
    __shared__ int s_carry;
    int tid = threadIdx.x, lane = tid & 31, wid = tid >> 5;
    if (tid == 0) s_carry = 0;
    __syncthreads();
    for (int base = 0; base < N; base += 256) {
        int i = base + tid;
        int v = (i < N) ? g_cnt[i] : 0;
        int x = v;
#pragma unroll
        for (int off = 1; off < 32; off <<= 1) {
            int t = __shfl_up_sync(0xffffffffu, x, off);
            if (lane >= off) x += t;
        }
        if (lane == 31) s_w[wid] = x;
        __syncthreads();
        int wb = 0;
        for (int w = 0; w < wid; w++) wb += s_w[w];
        int carry = s_carry;
        int excl = carry + wb + x - v;
        if (i < N) { g_off[i] = excl; g_pos[i] = excl; }
        __syncthreads();
        if (tid == 255) s_carry = carry + wb + x;
        __syncthreads();
    }
    if (threadIdx.x == 0) g_off[N] = s_carry;
}
__global__ void scatter_kernel(int Et) {
    int e = blockIdx.x * blockDim.x + threadIdx.x;
    if (e >= Et) return;
    int d = g_dst[e];
    int idx = atomicAdd(&g_pos[d], 1);
    g_eidx[idx] = g_src[e];
}

// ---------------- layer-1 GEMM: [N,18] @ [18,512] ----------------
__global__ void gemm18_kernel(const float* __restrict__ x, const float* __restrict__ W, int N) {
    __shared__ float sW[18 * 512];
    __shared__ float sx[32 * 18];
    for (int i = threadIdx.x; i < 18 * 512; i += 256) sW[i] = W[i];
    int n0 = blockIdx.x * 32;
    for (int i = threadIdx.x; i < 32 * 18; i += 256) {
        int n = n0 + i / 18;
        sx[i] = (n < N) ? x[n * 18 + i % 18] : 0.f;
    }
    __syncthreads();
    for (int o = threadIdx.x; o < 32 * 512; o += 256) {
        int nl = o >> 9, c = o & 511;
        int n = n0 + nl;
        if (n < N) {
            float acc = 0.f;
#pragma unroll
            for (int k = 0; k < 18; k++) acc += sx[nl * 18 + k] * sW[k * 512 + c];
            g_hw[n * 512 + c] = acc;
        }
    }
}

// ---------------- layers 2/3: TF32 tensor-core GEMM + fused alpha ----------------
// C[M,512] = g_x[M,512] @ B[512,512];   alpha fused: g_as/g_ad per (row, head)
// block tile 128x128, 8 warps (4 M x 2 N), warp tile 32x64 (= 32 rows of ONE head)
__global__ __launch_bounds__(256) void tf32gemm_kernel(
    const float* __restrict__ B,
    const float* __restrict__ a_src, const float* __restrict__ a_dst, int M) {
    __shared__ float As[128][36];   // [m][k], pad 36: frag banks r*4+k -> 0..31
    __shared__ float Bs[32][136];   // [k][n], pad 136: frag banks k*8+n -> 0..31
    __shared__ float sAs[2][64], sAd[2][64];

    int tid = threadIdx.x;
    int lane = tid & 31, wid = tid >> 5;
    int warpM = wid & 3, warpN = wid >> 2;
    int tig = lane & 3, gid4 = lane >> 2;
    int rowBase = blockIdx.y * 128, colBase = blockIdx.x * 128;

    // preload attention vectors for this block's 2 heads
    if (tid < 128) {
        int h = tid >> 6, c = tid & 63;
        int hg = blockIdx.x * 2 + h;
        sAs[h][c] = a_src[hg * 64 + c];
        sAd[h][c] = a_dst[hg * 64 + c];
    }

    float acc[2][8][4];
#pragma unroll
    for (int mt = 0; mt < 2; mt++)
#pragma unroll
        for (int nt = 0; nt < 8; nt++)
#pragma unroll
            for (int i = 0; i < 4; i++) acc[mt][nt][i] = 0.f;

    int aRow = tid >> 3, aC = (tid & 7);       // A: 4 iters of rows += 32
    int bRow = tid >> 5, bC = (tid & 31);      // B: 4 iters of rows += 8

    for (int kt = 0; kt < 512; kt += 32) {
        __syncthreads();
#pragma unroll
        for (int it = 0; it < 4; it++) {
            int r = aRow + it * 32;
            int gr = rowBase + r;
            float4 v = make_float4(0.f, 0.f, 0.f, 0.f);
            if (gr < M) v = *(const float4*)&g_x[(size_t)gr * 512 + kt + aC * 4];
            *(float4*)&As[r][aC * 4] = v;
        }
#pragma unroll
        for (int it = 0; it < 4; it++) {
            int kr = bRow + it * 8;
            float4 v = *(const float4*)&B[(size_t)(kt + kr) * 512 + colBase + bC * 4];
            *(float4*)&Bs[kr][bC * 4] = v;
        }
        __syncthreads();

#pragma unroll
        for (int ks = 0; ks < 4; ks++) {
            unsigned af[2][4], bf[8][2];
#pragma unroll
            for (int mt = 0; mt < 2; mt++) {
                int r = warpM * 32 + mt * 16 + gid4;
                af[mt][0] = f2tf(As[r][ks * 8 + tig]);
                af[mt][1] = f2tf(As[r + 8][ks * 8 + tig]);
                af[mt][2] = f2tf(As[r][ks * 8 + tig + 4]);
                af[mt][3] = f2tf(As[r + 8][ks * 8 + tig + 4]);
            }
#pragma unroll
            for (int nt = 0; nt < 8; nt++) {
                int cc = warpN * 64 + nt * 8 + gid4;
                bf[nt][0] = f2tf(Bs[ks * 8 + tig][cc]);
                bf[nt][1] = f2tf(Bs[ks * 8 + tig + 4][cc]);
            }
#pragma unroll
            for (int mt = 0; mt < 2; mt++)
#pragma unroll
                for (int nt = 0; nt < 8; nt++)
                    mma_tf32(acc[mt][nt], af[mt], bf[nt]);
        }
    }

    // epilogue: store C + fused alpha dots
    int head = blockIdx.x * 2 + warpN;
#pragma unroll
    for (int mt = 0; mt < 2; mt++) {
        int row0 = rowBase + warpM * 32 + mt * 16 + gid4;
        int row1 = row0 + 8;
        float ds0 = 0.f, dd0 = 0.f, ds1 = 0.f, dd1 = 0.f;
#pragma unroll
        for (int nt = 0; nt < 8; nt++) {
            int c0 = nt * 8 + 2 * tig;
            float as0 = sAs[warpN][c0], as1 = sAs[warpN][c0 + 1];
            float ad0 = sAd[warpN][c0], ad1 = sAd[warpN][c0 + 1];
            float* cc = acc[mt][nt];
            ds0 += cc[0] * as0 + cc[1] * as1;
            dd0 += cc[0] * ad0 + cc[1] * ad1;
            ds1 += cc[2] * as0 + cc[3] * as1;
            dd1 += cc[2] * ad0 + cc[3] * ad1;
            int colg = colBase + warpN * 64 + c0;
            if (row0 < M) *(float2*)&g_hw[(size_t)row0 * 512 + colg] = make_float2(cc[0], cc[1]);
            if (row1 < M) *(float2*)&g_hw[(size_t)row1 * 512 + colg] = make_float2(cc[2], cc[3]);
        }
#pragma unroll
        for (int o = 1; o < 4; o <<= 1) {
            ds0 += __shfl_xor_sync(0xffffffffu, ds0, o);
            dd0 += __shfl_xor_sync(0xffffffffu, dd0, o);
            ds1 += __shfl_xor_sync(0xffffffffu, ds1, o);
            dd1 += __shfl_xor_sync(0xffffffffu, dd1, o);
        }
        if (tig == 0) {
            if (row0 < M) { g_as[row0 * 8 + head] = ds0; g_ad[row0 * 8 + head] = dd0; }
            if (row1 < M) { g_as[row1 * 8 + head] = ds1; g_ad[row1 * 8 + head] = dd1; }
        }
    }
}

// ---------------- per-node attention coefficients (layer 1 only) ----------------
__global__ void alpha_kernel(const float* __restrict__ a_src, const float* __restrict__ a_dst, int N) {
    int gw = (blockIdx.x * blockDim.x + threadIdx.x) >> 5;
    int lane = threadIdx.x & 31;
    if (gw >= N * 8) return;
    int n = gw >> 3, h = gw & 7;
    const float* hp = &g_hw[(size_t)n * 512 + h * 64];
    float v0 = hp[lane], v1 = hp[lane + 32];
    const float* sp = &a_src[h * 64];
    const float* dp = &a_dst[h * 64];
    float ds = v0 * sp[lane] + v1 * sp[lane + 32];
    float dd = v0 * dp[lane] + v1 * dp[lane + 32];
#pragma unroll
    for (int o = 16; o; o >>= 1) {
        ds += __shfl_xor_sync(0xffffffffu, ds, o);
        dd += __shfl_xor_sync(0xffffffffu, dd, o);
    }
    if (!lane) { g_as[gw] = ds; g_ad[gw] = dd; }
}

// ---------------- fused per-dst softmax + aggregation (CSR, no atomics) ----------------
template <int MODE>
__global__ __launch_bounds__(128) void agg_csr_kernel(const float* __restrict__ bias) {
    int d = blockIdx.x;
    int tid = threadIdx.x;
    int beg = g_off[d], end = g_off[d + 1];

    __shared__ float s_m[8], s_den[8];
    __shared__ float s_part[64];
    __shared__ float s_w[16 * 8];
    __shared__ int   s_src[16];

    if (tid < 64) {
        int h = tid & 7, slot = tid >> 3;
        float adh = g_ad[d * 8 + h];
        float m = -1e30f;
        for (int j = beg + slot; j < end; j += 8) {
            float v = g_as[g_eidx[j] * 8 + h] + adh;
            v = v > 0.f ? v : 0.2f * v;
            m = fmaxf(m, v);
        }
        s_part[tid] = m;
    }
    __syncthreads();
    if (tid < 8) {
        float m = s_part[tid];
#pragma unroll
        for (int k = 1; k < 8; k++) m = fmaxf(m, s_part[tid + 8 * k]);
        s_m[tid] = m;
    }
    __syncthreads();
    if (tid < 64) {
        int h = tid & 7, slot = tid >> 3;
        float adh = g_ad[d * 8 + h], m = s_m[h], den = 0.f;
        for (int j = beg + slot; j < end; j += 8) {
            float v = g_as[g_eidx[j] * 8 + h] + adh;
            v = v > 0.f ? v : 0.2f * v;
            den += __expf(v - m);
        }
        s_part[tid] = den;
    }
    __syncthreads();
    if (tid < 8) {
        float den = 0.f;
#pragma unroll
        for (int k = 0; k < 8; k++) den += s_part[tid + 8 * k];
        s_den[tid] = __fdividef(1.f, den + 1e-16f);
    }

    int head = tid >> 4;
    float4 acc = make_float4(0.f, 0.f, 0.f, 0.f);
    for (int c0 = beg; c0 < end; c0 += 16) {
        int nc = min(16, end - c0);
        __syncthreads();
        if (tid < nc) s_src[tid] = g_eidx[c0 + tid];
        __syncthreads();
        {
            int j = tid >> 3, h = tid & 7;
            if (j < nc) {
                float v = g_as[s_src[j] * 8 + h] + g_ad[d * 8 + h];
                v = v > 0.f ? v : 0.2f * v;
                s_w[j * 8 + h] = __expf(v - s_m[h]) * s_den[h];
            }
        }
        __syncthreads();
#pragma unroll 4
        for (int j = 0; j < nc; j++) {
            float w = s_w[j * 8 + head];
            float4 hv = *(const float4*)&g_hw[(size_t)s_src[j] * 512 + tid * 4];
            acc.x += hv.x * w; acc.y += hv.y * w;
            acc.z += hv.z * w; acc.w += hv.w * w;
        }
    }

    if (MODE == 0) {
        float4 bb = *(const float4*)&bias[tid * 4];
        acc.x += bb.x; acc.y += bb.y; acc.z += bb.z; acc.w += bb.w;
        acc.x = acc.x > 0.f ? acc.x : expm1f(acc.x);
        acc.y = acc.y > 0.f ? acc.y : expm1f(acc.y);
        acc.z = acc.z > 0.f ? acc.z : expm1f(acc.z);
        acc.w = acc.w > 0.f ? acc.w : expm1f(acc.w);
        *(float4*)&g_x[(size_t)d * 512 + tid * 4] = acc;
    } else {
        *(float4*)&g_out[(size_t)d * 512 + tid * 4] = acc;
    }
}

// ---------------- epilogues ----------------
__global__ void mean_kernel(const float* __restrict__ b3, int N) {
    int i = blockIdx.x * blockDim.x + threadIdx.x;
    if (i >= N * 64) return;
    int n = i >> 6, c = i & 63;
    float acc = 0.f;
#pragma unroll
    for (int h = 0; h < 8; h++) acc += g_out[(size_t)n * 512 + h * 64 + c];
    g_x[n * 64 + c] = acc * 0.125f + b3[c];
}

__global__ void final_kernel(const float* __restrict__ Wo, const float* __restrict__ bo,
                             float* __restrict__ out, int N) {
    __shared__ float sW[64 * 15];
    __shared__ float sb[15];
    for (int i = threadIdx.x; i < 64 * 15; i += 256) sW[i] = Wo[i];
    if (threadIdx.x < 15) sb[threadIdx.x] = bo[threadIdx.x];
    __syncthreads();
    int gid = blockIdx.x * 256 + threadIdx.x;
    if (gid >= N * 15) return;
    int n = gid / 15, o = gid - n * 15;
    float acc = sb[o];
#pragma unroll
    for (int c = 0; c < 64; c++) acc += g_x[n * 64 + c] * sW[c * 15 + o];
    out[gid] = acc;
}

// ---------------- launch ----------------
extern "C" void kernel_launch(void* const* d_in, const int* in_sizes, int n_in,
                              void* d_out, int out_size) {
    const float* x   = (const float*)d_in[0];
    const void*  ei  = (const void*)d_in[1];
    const float* W1  = (const float*)d_in[2];
    const float* a1s = (const float*)d_in[3];
    const float* a1d = (const float*)d_in[4];
    const float* b1  = (const float*)d_in[5];
    const float* W2  = (const float*)d_in[6];
    const float* a2s = (const float*)d_in[7];
    const float* a2d = (const float*)d_in[8];
    const float* b2  = (const float*)d_in[9];
    const float* W3  = (const float*)d_in[10];
    const float* a3s = (const float*)d_in[11];
    const float* a3d = (const float*)d_in[12];
    const float* b3  = (const float*)d_in[13];
    const float* Wo  = (const float*)d_in[14];
    const float* bo  = (const float*)d_in[15];

    int N  = in_sizes[0] / 18;
    int E0 = in_sizes[1] / 2;
    int Et = E0 + N;

    int gE = (Et + 255) / 256;
    int gN = (N + 255) / 256;
    int gA = (N * 8 * 32 + 255) / 256;
    dim3 gG(4, (N + 127) / 128);

    // edge decode + CSR build (once)
    detect_kernel<<<1, 32>>>(ei, E0, N);
    decode_kernel<<<gE, 256>>>(ei, E0, N);
    zero_cnt_kernel<<<gN, 256>>>(N);
    hist_kernel<<<gE, 256>>>(Et);
    scan_kernel<<<1, 256>>>(N);
    scatter_kernel<<<gE, 256>>>(Et);

    // ---- layer 1 ----
    gemm18_kernel<<<(N + 31) / 32, 256>>>(x, W1, N);
    alpha_kernel<<<gA, 256>>>(a1s, a1d, N);
    agg_csr_kernel<0><<<N, 128>>>(b1);

    // ---- layer 2 ----
    tf32gemm_kernel<<<gG, 256>>>(W2, a2s, a2d, N);
    agg_csr_kernel<0><<<N, 128>>>(b2);

    // ---- layer 3 ----
    tf32gemm_kernel<<<gG, 256>>>(W3, a3s, a3d, N);
    agg_csr_kernel<1><<<N, 128>>>(nullptr);

    mean_kernel<<<(N * 64 + 255) / 256, 256>>>(b3, N);
    final_kernel<<<(N * 15 + 255) / 256, 256>>>(Wo, bo, (float*)d_out, N);
}

// round 5
// speedup vs baseline: 3.0095x; 1.0552x over previous
#include <cuda_runtime.h>
#include <math.h>

#define HEADS 8
#define HID 64
#define HCdim 512
#define NMAXc 50000
#define EMAXc 450000   // 400000 edges + 50000 self loops

// ---------------- scratch ----------------
__device__ __align__(16) float g_x  [NMAXc * HCdim];   // layer input / elu output
__device__ __align__(16) float g_hw [NMAXc * HCdim];   // h = x @ W
__device__ __align__(16) float g_out[NMAXc * HCdim];   // layer-3 raw aggregation
__device__ __align__(16) float g_W  [HCdim * HCdim];   // tf32-rounded weight matrix
__device__ __align__(16) float g_as [NMAXc * HEADS];
__device__ __align__(16) float g_ad [NMAXc * HEADS];
__device__ int g_src[EMAXc];
__device__ int g_dst[EMAXc];
__device__ int g_eidx[EMAXc];        // src ids grouped by dst (CSR)
__device__ int g_cnt[NMAXc];
__device__ int g_off[NMAXc + 1];
__device__ int g_pos[NMAXc];
__device__ int g_is64;

// ---------------- helpers ----------------
__device__ __forceinline__ unsigned f2tf(float f) {
    unsigned r;
    asm("cvt.rna.tf32.f32 %0, %1;" : "=r"(r) : "f"(f));
    return r;
}
__device__ __forceinline__ void mma_tf32(float* c, const unsigned* a, const unsigned* b) {
    asm volatile(
        "mma.sync.aligned.m16n8k8.row.col.f32.tf32.tf32.f32 "
        "{%0,%1,%2,%3}, {%4,%5,%6,%7}, {%8,%9}, {%0,%1,%2,%3};"
        : "+f"(c[0]), "+f"(c[1]), "+f"(c[2]), "+f"(c[3])
        : "r"(a[0]), "r"(a[1]), "r"(a[2]), "r"(a[3]), "r"(b[0]), "r"(b[1]));
}

// ---------------- edge index dtype probe + decode ----------------
__global__ void detect_kernel(const void* __restrict__ ei, int E0, int N) {
    if (threadIdx.x == 0 && blockIdx.x == 0) {
        const long long* p = (const long long*)ei;
        int K = E0 < 64 ? E0 : 64;
        int ok = 1;
        for (int i = 0; i < K; i++) {
            long long v = p[i];
            if (v < 0 || v >= N) { ok = 0; break; }
        }
        g_is64 = ok;
    }
}

__global__ void decode_kernel(const void* __restrict__ ei, int E0, int N) {
    int e = blockIdx.x * blockDim.x + threadIdx.x;
    int Et = E0 + N;
    if (e >= Et) return;
    int s, d;
    if (e < E0) {
        if (g_is64) {
            const long long* p = (const long long*)ei;
            s = (int)p[e]; d = (int)p[E0 + e];
        } else {
            const int* p = (const int*)ei;
            s = p[e]; d = p[E0 + e];
        }
    } else {
        s = d = e - E0;
    }
    s = min(max(s, 0), N - 1);
    d = min(max(d, 0), N - 1);
    g_src[e] = s;
    g_dst[e] = d;
}

// ---------------- CSR build ----------------
__global__ void zero_cnt_kernel(int N) {
    int i = blockIdx.x * blockDim.x + threadIdx.x;
    if (i < N) g_cnt[i] = 0;
}
__global__ void hist_kernel(int Et) {
    int e = blockIdx.x * blockDim.x + threadIdx.x;
    if (e < Et) atomicAdd(&g_cnt[g_dst[e]], 1);
}
__global__ void scan_kernel(int N) {
    __shared__ int s_w[8];
    __shared__ int s_carry;
    int tid = threadIdx.x, lane = tid & 31, wid = tid >> 5;
    if (tid == 0) s_carry = 0;
    __syncthreads();
    for (int base = 0; base < N; base += 256) {
        int i = base + tid;
        int v = (i < N) ? g_cnt[i] : 0;
        int x = v;
#pragma unroll
        for (int off = 1; off < 32; off <<= 1) {
            int t = __shfl_up_sync(0xffffffffu, x, off);
            if (lane >= off) x += t;
        }
        if (lane == 31) s_w[wid] = x;
        __syncthreads();
        int wb = 0;
        for (int w = 0; w < wid; w++) wb += s_w[w];
        int carry = s_carry;
        int excl = carry + wb + x - v;
        if (i < N) { g_off[i] = excl; g_pos[i] = excl; }
        __syncthreads();
        if (tid == 255) s_carry = carry + wb + x;
        __syncthreads();
    }
    if (threadIdx.x == 0) g_off[N] = s_carry;
}
__global__ void scatter_kernel(int Et) {
    int e = blockIdx.x * blockDim.x + threadIdx.x;
    if (e >= Et) return;
    int d = g_dst[e];
    int idx = atomicAdd(&g_pos[d], 1);
    g_eidx[idx] = g_src[e];
}

// ---------------- weight pre-conversion to tf32 ----------------
__global__ void cvtW_kernel(const float* __restrict__ W) {
    int i = blockIdx.x * blockDim.x + threadIdx.x;
    if (i < 512 * 512) g_W[i] = __uint_as_float(f2tf(W[i]));
}

// ---------------- layer-1 GEMM: [N,18] @ [18,512] ----------------
__global__ void gemm18_kernel(const float* __restrict__ x, const float* __restrict__ W, int N) {
    __shared__ float sW[18 * 512];
    __shared__ float sx[32 * 18];
    for (int i = threadIdx.x; i < 18 * 512; i += 256) sW[i] = W[i];
    int n0 = blockIdx.x * 32;
    for (int i = threadIdx.x; i < 32 * 18; i += 256) {
        int n = n0 + i / 18;
        sx[i] = (n < N) ? x[n * 18 + i % 18] : 0.f;
    }
    __syncthreads();
    for (int o = threadIdx.x; o < 32 * 512; o += 256) {
        int nl = o >> 9, c = o & 511;
        int n = n0 + nl;
        if (n < N) {
            float acc = 0.f;
#pragma unroll
            for (int k = 0; k < 18; k++) acc += sx[nl * 18 + k] * sW[k * 512 + c];
            g_hw[n * 512 + c] = acc;
        }
    }
}

// ---------------- layers 2/3: TF32 tensor-core GEMM + fused alpha ----------------
// C[M,512] = g_x[M,512] @ g_W[512,512] (g_W pre-rounded to tf32)
// block tile 128x128, 8 warps (4 M x 2 N), warp tile 32x64 (= 32 rows of ONE head)
__global__ __launch_bounds__(256) void tf32gemm_kernel(
    const float* __restrict__ a_src, const float* __restrict__ a_dst, int M) {
    __shared__ float As[128][36];   // [m][k], tf32-rounded at store
    __shared__ float Bs[32][136];   // [k][n], already tf32-rounded (g_W)
    __shared__ float sAs[2][64], sAd[2][64];

    int tid = threadIdx.x;
    int lane = tid & 31, wid = tid >> 5;
    int warpM = wid & 3, warpN = wid >> 2;
    int tig = lane & 3, gid4 = lane >> 2;
    int rowBase = blockIdx.y * 128, colBase = blockIdx.x * 128;

    if (tid < 128) {
        int h = tid >> 6, c = tid & 63;
        int hg = blockIdx.x * 2 + h;
        sAs[h][c] = a_src[hg * 64 + c];
        sAd[h][c] = a_dst[hg * 64 + c];
    }

    float acc[2][8][4];
#pragma unroll
    for (int mt = 0; mt < 2; mt++)
#pragma unroll
        for (int nt = 0; nt < 8; nt++)
#pragma unroll
            for (int i = 0; i < 4; i++) acc[mt][nt][i] = 0.f;

    int aRow = tid >> 3, aC = (tid & 7);
    int bRow = tid >> 5, bC = (tid & 31);

    for (int kt = 0; kt < 512; kt += 32) {
        __syncthreads();
#pragma unroll
        for (int it = 0; it < 4; it++) {
            int r = aRow + it * 32;
            int gr = rowBase + r;
            float4 v = make_float4(0.f, 0.f, 0.f, 0.f);
            if (gr < M) v = *(const float4*)&g_x[(size_t)gr * 512 + kt + aC * 4];
            As[r][aC * 4 + 0] = __uint_as_float(f2tf(v.x));
            As[r][aC * 4 + 1] = __uint_as_float(f2tf(v.y));
            As[r][aC * 4 + 2] = __uint_as_float(f2tf(v.z));
            As[r][aC * 4 + 3] = __uint_as_float(f2tf(v.w));
        }
#pragma unroll
        for (int it = 0; it < 4; it++) {
            int kr = bRow + it * 8;
            float4 v = *(const float4*)&g_W[(size_t)(kt + kr) * 512 + colBase + bC * 4];
            *(float4*)&Bs[kr][bC * 4] = v;
        }
        __syncthreads();

#pragma unroll
        for (int ks = 0; ks < 4; ks++) {
            unsigned af[2][4], bf[8][2];
#pragma unroll
            for (int mt = 0; mt < 2; mt++) {
                int r = warpM * 32 + mt * 16 + gid4;
                af[mt][0] = __float_as_uint(As[r][ks * 8 + tig]);
                af[mt][1] = __float_as_uint(As[r + 8][ks * 8 + tig]);
                af[mt][2] = __float_as_uint(As[r][ks * 8 + tig + 4]);
                af[mt][3] = __float_as_uint(As[r + 8][ks * 8 + tig + 4]);
            }
#pragma unroll
            for (int nt = 0; nt < 8; nt++) {
                int cc = warpN * 64 + nt * 8 + gid4;
                bf[nt][0] = __float_as_uint(Bs[ks * 8 + tig][cc]);
                bf[nt][1] = __float_as_uint(Bs[ks * 8 + tig + 4][cc]);
            }
#pragma unroll
            for (int mt = 0; mt < 2; mt++)
#pragma unroll
                for (int nt = 0; nt < 8; nt++)
                    mma_tf32(acc[mt][nt], af[mt], bf[nt]);
        }
    }

    int head = blockIdx.x * 2 + warpN;
#pragma unroll
    for (int mt = 0; mt < 2; mt++) {
        int row0 = rowBase + warpM * 32 + mt * 16 + gid4;
        int row1 = row0 + 8;
        float ds0 = 0.f, dd0 = 0.f, ds1 = 0.f, dd1 = 0.f;
#pragma unroll
        for (int nt = 0; nt < 8; nt++) {
            int c0 = nt * 8 + 2 * tig;
            float as0 = sAs[warpN][c0], as1 = sAs[warpN][c0 + 1];
            float ad0 = sAd[warpN][c0], ad1 = sAd[warpN][c0 + 1];
            float* cc = acc[mt][nt];
            ds0 += cc[0] * as0 + cc[1] * as1;
            dd0 += cc[0] * ad0 + cc[1] * ad1;
            ds1 += cc[2] * as0 + cc[3] * as1;
            dd1 += cc[2] * ad0 + cc[3] * ad1;
            int colg = colBase + warpN * 64 + c0;
            if (row0 < M) *(float2*)&g_hw[(size_t)row0 * 512 + colg] = make_float2(cc[0], cc[1]);
            if (row1 < M) *(float2*)&g_hw[(size_t)row1 * 512 + colg] = make_float2(cc[2], cc[3]);
        }
#pragma unroll
        for (int o = 1; o < 4; o <<= 1) {
            ds0 += __shfl_xor_sync(0xffffffffu, ds0, o);
            dd0 += __shfl_xor_sync(0xffffffffu, dd0, o);
            ds1 += __shfl_xor_sync(0xffffffffu, ds1, o);
            dd1 += __shfl_xor_sync(0xffffffffu, dd1, o);
        }
        if (tig == 0) {
            if (row0 < M) { g_as[row0 * 8 + head] = ds0; g_ad[row0 * 8 + head] = dd0; }
            if (row1 < M) { g_as[row1 * 8 + head] = ds1; g_ad[row1 * 8 + head] = dd1; }
        }
    }
}

// ---------------- per-node attention coefficients (layer 1 only) ----------------
__global__ void alpha_kernel(const float* __restrict__ a_src, const float* __restrict__ a_dst, int N) {
    int gw = (blockIdx.x * blockDim.x + threadIdx.x) >> 5;
    int lane = threadIdx.x & 31;
    if (gw >= N * 8) return;
    int n = gw >> 3, h = gw & 7;
    const float* hp = &g_hw[(size_t)n * 512 + h * 64];
    float v0 = hp[lane], v1 = hp[lane + 32];
    const float* sp = &a_src[h * 64];
    const float* dp = &a_dst[h * 64];
    float ds = v0 * sp[lane] + v1 * sp[lane + 32];
    float dd = v0 * dp[lane] + v1 * dp[lane + 32];
#pragma unroll
    for (int o = 16; o; o >>= 1) {
        ds += __shfl_xor_sync(0xffffffffu, ds, o);
        dd += __shfl_xor_sync(0xffffffffu, dd, o);
    }
    if (!lane) { g_as[gw] = ds; g_ad[gw] = dd; }
}

// ---------------- fused softmax + aggregation: warp per (dst, 2 heads) ----------------
// warp w of block handles heads {2w, 2w+1} = cols [w*128, w*128+128) of dst row.
// Online softmax (single stats pass), no shared memory, no barriers.
template <int MODE>
__global__ __launch_bounds__(128) void agg_warp_kernel(const float* __restrict__ bias) {
    int d = blockIdx.x;
    int lane = threadIdx.x & 31, w = threadIdx.x >> 5;
    int beg = g_off[d], end = g_off[d + 1];
    int h0 = w * 2;
    int colBase = w * 128 + lane * 4;      // lanes 0-15: head h0 cols; 16-31: head h0+1
    int eh = h0 + (lane & 1);              // head this lane evaluates edge scores for
    float adh = g_ad[d * 8 + eh];

    // ---- single-pass online softmax stats (per parity class = per head) ----
    float m = -1e30f, den = 0.f;
    for (int c0 = beg; c0 < end; c0 += 16) {
        int j = c0 + (lane >> 1);
        float e = -1e30f;
        if (j < end) {
            int s = g_eidx[j];
            float v = g_as[s * 8 + eh] + adh;
            e = v > 0.f ? v : 0.2f * v;
        }
        float mc = e;
#pragma unroll
        for (int o = 2; o < 32; o <<= 1) mc = fmaxf(mc, __shfl_xor_sync(0xffffffffu, mc, o));
        float mn = fmaxf(m, mc);
        den *= __expf(m - mn);
        float ex = (j < end) ? __expf(e - mn) : 0.f;
#pragma unroll
        for (int o = 2; o < 32; o <<= 1) ex += __shfl_xor_sync(0xffffffffu, ex, o);
        den += ex;
        m = mn;
    }
    float rden = __fdividef(1.f, den + 1e-16f);

    // ---- weighted aggregation ----
    int hsel = lane >> 4;                  // which of the 2 heads my cols belong to
    float4 acc = make_float4(0.f, 0.f, 0.f, 0.f);
    for (int c0 = beg; c0 < end; c0 += 16) {
        int j = c0 + (lane >> 1);
        float wgt = 0.f;
        int s = 0;
        if (j < end) {
            s = g_eidx[j];
            float v = g_as[s * 8 + eh] + adh;
            v = v > 0.f ? v : 0.2f * v;
            wgt = __expf(v - m) * rden;
        }
        int nc = min(16, end - c0);
        for (int jj = 0; jj < nc; jj++) {
            float wj = __shfl_sync(0xffffffffu, wgt, jj * 2 + hsel);
            int   sj = __shfl_sync(0xffffffffu, s, jj * 2);
            float4 hv = *(const float4*)&g_hw[(size_t)sj * 512 + colBase];
            acc.x += hv.x * wj; acc.y += hv.y * wj;
            acc.z += hv.z * wj; acc.w += hv.w * wj;
        }
    }

    if (MODE == 0) {
        float4 bb = *(const float4*)&bias[colBase];
        acc.x += bb.x; acc.y += bb.y; acc.z += bb.z; acc.w += bb.w;
        acc.x = acc.x > 0.f ? acc.x : expm1f(acc.x);
        acc.y = acc.y > 0.f ? acc.y : expm1f(acc.y);
        acc.z = acc.z > 0.f ? acc.z : expm1f(acc.z);
        acc.w = acc.w > 0.f ? acc.w : expm1f(acc.w);
        *(float4*)&g_x[(size_t)d * 512 + colBase] = acc;
    } else {
        *(float4*)&g_out[(size_t)d * 512 + colBase] = acc;
    }
}

// ---------------- epilogues ----------------
__global__ void mean_kernel(const float* __restrict__ b3, int N) {
    int i = blockIdx.x * blockDim.x + threadIdx.x;
    if (i >= N * 64) return;
    int n = i >> 6, c = i & 63;
    float acc = 0.f;
#pragma unroll
    for (int h = 0; h < 8; h++) acc += g_out[(size_t)n * 512 + h * 64 + c];
    g_x[n * 64 + c] = acc * 0.125f + b3[c];
}

__global__ void final_kernel(const float* __restrict__ Wo, const float* __restrict__ bo,
                             float* __restrict__ out, int N) {
    __shared__ float sW[64 * 15];
    __shared__ float sb[15];
    for (int i = threadIdx.x; i < 64 * 15; i += 256) sW[i] = Wo[i];
    if (threadIdx.x < 15) sb[threadIdx.x] = bo[threadIdx.x];
    __syncthreads();
    int gid = blockIdx.x * 256 + threadIdx.x;
    if (gid >= N * 15) return;
    int n = gid / 15, o = gid - n * 15;
    float acc = sb[o];
#pragma unroll
    for (int c = 0; c < 64; c++) acc += g_x[n * 64 + c] * sW[c * 15 + o];
    out[gid] = acc;
}

// ---------------- launch ----------------
extern "C" void kernel_launch(void* const* d_in, const int* in_sizes, int n_in,
                              void* d_out, int out_size) {
    const float* x   = (const float*)d_in[0];
    const void*  ei  = (const void*)d_in[1];
    const float* W1  = (const float*)d_in[2];
    const float* a1s = (const float*)d_in[3];
    const float* a1d = (const float*)d_in[4];
    const float* b1  = (const float*)d_in[5];
    const float* W2  = (const float*)d_in[6];
    const float* a2s = (const float*)d_in[7];
    const float* a2d = (const float*)d_in[8];
    const float* b2  = (const float*)d_in[9];
    const float* W3  = (const float*)d_in[10];
    const float* a3s = (const float*)d_in[11];
    const float* a3d = (const float*)d_in[12];
    const float* b3  = (const float*)d_in[13];
    const float* Wo  = (const float*)d_in[14];
    const float* bo  = (const float*)d_in[15];

    int N  = in_sizes[0] / 18;
    int E0 = in_sizes[1] / 2;
    int Et = E0 + N;

    int gE = (Et + 255) / 256;
    int gN = (N + 255) / 256;
    int gA = (N * 8 * 32 + 255) / 256;
    dim3 gG(4, (N + 127) / 128);

    // edge decode + CSR build (once)
    detect_kernel<<<1, 32>>>(ei, E0, N);
    decode_kernel<<<gE, 256>>>(ei, E0, N);
    zero_cnt_kernel<<<gN, 256>>>(N);
    hist_kernel<<<gE, 256>>>(Et);
    scan_kernel<<<1, 256>>>(N);
    scatter_kernel<<<gE, 256>>>(Et);

    // ---- layer 1 ----
    gemm18_kernel<<<(N + 31) / 32, 256>>>(x, W1, N);
    alpha_kernel<<<gA, 256>>>(a1s, a1d, N);
    agg_warp_kernel<0><<<N, 128>>>(b1);

    // ---- layer 2 ----
    cvtW_kernel<<<1024, 256>>>(W2);
    tf32gemm_kernel<<<gG, 256>>>(a2s, a2d, N);
    agg_warp_kernel<0><<<N, 128>>>(b2);

    // ---- layer 3 ----
    cvtW_kernel<<<1024, 256>>>(W3);
    tf32gemm_kernel<<<gG, 256>>>(a3s, a3d, N);
    agg_warp_kernel<1><<<N, 128>>>(nullptr);

    mean_kernel<<<(N * 64 + 255) / 256, 256>>>(b3, N);
    final_kernel<<<(N * 15 + 255) / 256, 256>>>(Wo, bo, (float*)d_out, N);
}